// round 13
// baseline (speedup 1.0000x reference)
#include <cuda_runtime.h>
#include <math.h>

#define NB 512      // batch
#define NT 32       // timesteps
#define ND 512      // depth
#define NC 128      // classes
#define NR 512      // rnn hidden
#define NG 2048     // 4*rnn
#define KX 640      // depth + ncc

typedef unsigned long long ull;

__device__ float g_Z[(size_t)NB * NT * NG];   // 128 MiB
__device__ float g_P[4][(size_t)NB * NG];     // 16 MiB partial gate sums
__device__ float g_h[2][NB * NR];
__device__ float g_c[NB * NR];

// ---------------------------------------------------------------------------
__device__ __forceinline__ ull pack2(float x, float y) {
    ull r; asm("mov.b64 %0, {%1, %2};" : "=l"(r) : "f"(x), "f"(y)); return r;
}
__device__ __forceinline__ void unpack2(ull v, float& x, float& y) {
    asm("mov.b64 {%0, %1}, %2;" : "=f"(x), "=f"(y) : "l"(v));
}
__device__ __forceinline__ void ffma2(ull& d, ull a, ull b) {
    asm("fma.rn.f32x2 %0, %1, %2, %0;" : "+l"(d) : "l"(a), "l"(b));
}

// ---------------------------------------------------------------------------
__global__ void k_init() {
    int i = blockIdx.x * blockDim.x + threadIdx.x;
    if (i < NB * NR) { g_h[0][i] = 0.f; g_c[i] = 0.f; }
}

// ---------------------------------------------------------------------------
// Precompute Z = X @ kernel + bias    (M=16384, K=640, N=2048)  [proven]
// ---------------------------------------------------------------------------
__global__ void __launch_bounds__(256, 2) k_precompute(
    const float* __restrict__ f_pool,
    const float* __restrict__ gt,
    const float* __restrict__ W,
    const float* __restrict__ bias)
{
    __shared__ float As[16][128];
    __shared__ float Bs[16][128];
    const int tid = threadIdx.x;
    const int tx = tid & 15, ty = tid >> 4;
    const int m0 = blockIdx.y * 128;
    const int n0 = blockIdx.x * 128;
    const int t  = m0 >> 9;
    const int b0 = m0 & 511;

    ull acc[8][4];
#pragma unroll
    for (int i = 0; i < 8; i++)
#pragma unroll
        for (int p = 0; p < 4; p++) acc[i][p] = 0ull;

    const int aIdx = tid * 2;

    for (int k0 = 0; k0 < KX; k0 += 16) {
#pragma unroll
        for (int l = 0; l < 2; l++) {
            int q   = aIdx + l;
            int row = q >> 2;
            int kq  = (q & 3) << 2;
            int k   = k0 + kq;
            float4 v;
            if (k < ND) {
                v = *(const float4*)(f_pool + ((size_t)(b0 + row) * NT + t) * ND + k);
            } else if (t == 0) {
                v = make_float4(0.f, 0.f, 0.f, 0.f);
            } else {
                v = *(const float4*)(gt + ((size_t)(b0 + row) * NT + (t - 1)) * NC + (k - ND));
            }
            As[kq + 0][row] = v.x; As[kq + 1][row] = v.y;
            As[kq + 2][row] = v.z; As[kq + 3][row] = v.w;
        }
#pragma unroll
        for (int l = 0; l < 2; l++) {
            int q   = aIdx + l;
            int row = q >> 5;
            int cq  = (q & 31) << 2;
            *(float4*)&Bs[row][cq] =
                *(const float4*)(W + (size_t)(k0 + row) * NG + n0 + cq);
        }
        __syncthreads();

#pragma unroll
        for (int k = 0; k < 16; k++) {
            float a[8];
            *(float4*)&a[0] = *(float4*)&As[k][ty * 4];
            *(float4*)&a[4] = *(float4*)&As[k][64 + ty * 4];
            ull bp[4];
            bp[0] = *(const ull*)&Bs[k][tx * 4];
            bp[1] = *(const ull*)&Bs[k][tx * 4 + 2];
            bp[2] = *(const ull*)&Bs[k][64 + tx * 4];
            bp[3] = *(const ull*)&Bs[k][64 + tx * 4 + 2];
            ull ad[8];
#pragma unroll
            for (int i = 0; i < 8; i++) ad[i] = pack2(a[i], a[i]);
#pragma unroll
            for (int i = 0; i < 8; i++)
#pragma unroll
                for (int p = 0; p < 4; p++)
                    ffma2(acc[i][p], ad[i], bp[p]);
        }
        __syncthreads();
    }

#pragma unroll
    for (int ih = 0; ih < 2; ih++)
#pragma unroll
    for (int ii = 0; ii < 4; ii++) {
        int m = m0 + ih * 64 + ty * 4 + ii;
        int i = ih * 4 + ii;
#pragma unroll
        for (int jh = 0; jh < 2; jh++) {
            int n = n0 + jh * 64 + tx * 4;
            float4 v;
            unpack2(acc[i][jh * 2 + 0], v.x, v.y);
            unpack2(acc[i][jh * 2 + 1], v.z, v.w);
            v.x += bias[n + 0]; v.y += bias[n + 1];
            v.z += bias[n + 2]; v.w += bias[n + 3];
            *(float4*)&g_Z[(size_t)m * NG + n] = v;
        }
    }
}

// ---------------------------------------------------------------------------
// Shared overlay for k_gemm (GEMM role 16 KB; logits role ~24.6 KB)
// ---------------------------------------------------------------------------
union GemmSM {
    struct { float As[16][128]; float Bs[16][128]; } g;
    struct { float2 hsp[4][NR]; float2 part[4][NC];
             float lgs[8][NC]; int amax[8]; } l;
};

// ---------------------------------------------------------------------------
// GEMM role: partial h @ rec over one K-chunk of 128.
// 128x128 tile, 8x8/thread, BK=16 (8 tiles), register prefetch.
// bid 0..255: chunk = bid>>6 (0..3), tile = bid&63 (mtile = tile>>4, ntile&15)
// ---------------------------------------------------------------------------
__device__ void do_gemm(GemmSM& sm, const float* __restrict__ rec,
                        int t, int bid)
{
    const int tid = threadIdx.x;          // 256
    const int tx = tid & 15, ty = tid >> 4;
    const int chunk = bid >> 6;
    const int tile  = bid & 63;
    const int m0 = (tile >> 4) * 128;
    const int n0 = (tile & 15) * 128;
    const int kb = chunk * 128;
    const float* __restrict__ h_in = g_h[t & 1];
    float* __restrict__ P = g_P[chunk];

    ull acc[8][4];
#pragma unroll
    for (int i = 0; i < 8; i++)
#pragma unroll
        for (int p = 0; p < 4; p++) acc[i][p] = 0ull;

    const int q0 = tid * 2, q1 = q0 + 1;
    const int ar0 = q0 >> 2, ak0 = (q0 & 3) << 2;
    const int ar1 = q1 >> 2, ak1 = (q1 & 3) << 2;
    const int br0 = q0 >> 5, bc0 = (q0 & 31) << 2;
    const int br1 = q1 >> 5, bc1 = (q1 & 31) << 2;
    const float* ap0 = h_in + (size_t)(m0 + ar0) * NR + kb + ak0;
    const float* ap1 = h_in + (size_t)(m0 + ar1) * NR + kb + ak1;
    const float* bq0 = rec + (size_t)(kb + br0) * NG + n0 + bc0;
    const float* bq1 = rec + (size_t)(kb + br1) * NG + n0 + bc1;

    float4 ra0 = *(const float4*)ap0;
    float4 ra1 = *(const float4*)ap1;
    float4 rb0 = *(const float4*)bq0;
    float4 rb1 = *(const float4*)bq1;

    for (int tl = 0; tl < 8; tl++) {
        sm.g.As[ak0 + 0][ar0] = ra0.x; sm.g.As[ak0 + 1][ar0] = ra0.y;
        sm.g.As[ak0 + 2][ar0] = ra0.z; sm.g.As[ak0 + 3][ar0] = ra0.w;
        sm.g.As[ak1 + 0][ar1] = ra1.x; sm.g.As[ak1 + 1][ar1] = ra1.y;
        sm.g.As[ak1 + 2][ar1] = ra1.z; sm.g.As[ak1 + 3][ar1] = ra1.w;
        *(float4*)&sm.g.Bs[br0][bc0] = rb0;
        *(float4*)&sm.g.Bs[br1][bc1] = rb1;
        __syncthreads();

        if (tl < 7) {
            const int ko = (tl + 1) * 16;
            ra0 = *(const float4*)(ap0 + ko);
            ra1 = *(const float4*)(ap1 + ko);
            rb0 = *(const float4*)(bq0 + (size_t)ko * NG);
            rb1 = *(const float4*)(bq1 + (size_t)ko * NG);
        }

#pragma unroll
        for (int k = 0; k < 16; k++) {
            float a[8];
            *(float4*)&a[0] = *(float4*)&sm.g.As[k][ty * 4];
            *(float4*)&a[4] = *(float4*)&sm.g.As[k][64 + ty * 4];
            ull bp[4];
            bp[0] = *(const ull*)&sm.g.Bs[k][tx * 4];
            bp[1] = *(const ull*)&sm.g.Bs[k][tx * 4 + 2];
            bp[2] = *(const ull*)&sm.g.Bs[k][64 + tx * 4];
            bp[3] = *(const ull*)&sm.g.Bs[k][64 + tx * 4 + 2];
            ull ad[8];
#pragma unroll
            for (int i = 0; i < 8; i++) ad[i] = pack2(a[i], a[i]);
#pragma unroll
            for (int i = 0; i < 8; i++)
#pragma unroll
                for (int p = 0; p < 4; p++)
                    ffma2(acc[i][p], ad[i], bp[p]);
        }
        __syncthreads();
    }

#pragma unroll
    for (int ih = 0; ih < 2; ih++)
#pragma unroll
    for (int ii = 0; ii < 4; ii++) {
        int m = m0 + ih * 64 + ty * 4 + ii;
        int i = ih * 4 + ii;
#pragma unroll
        for (int jh = 0; jh < 2; jh++) {
            int n = n0 + jh * 64 + tx * 4;
            float4 v;
            unpack2(acc[i][jh * 2 + 0], v.x, v.y);
            unpack2(acc[i][jh * 2 + 1], v.z, v.w);
            *(float4*)&P[(size_t)m * NG + n] = v;
        }
    }
}

// ---------------------------------------------------------------------------
// Logits role (256 thr): 32 rows/block in 4 groups of 8; 2-way k-split.
// 16 blocks. lt = emitted timestep; reads g_h[(lt+1)&1].
// ---------------------------------------------------------------------------
__device__ void do_logits256(GemmSM& sm,
                             const float* __restrict__ sw,
                             const float* __restrict__ sb,
                             float* __restrict__ out, int lt, int lbid)
{
    const int tid = threadIdx.x;          // 256
    const int j   = tid & 127;
    const int kq  = tid >> 7;             // 0/1
    const float* __restrict__ h = g_h[(lt + 1) & 1];
    const float bj = sb[j];

    for (int grp = 0; grp < 4; grp++) {
        const int b0 = lbid * 32 + grp * 8;

#pragma unroll
        for (int r = 0; r < 8; r++) {
#pragma unroll
            for (int kk = 0; kk < 2; kk++) {
                int k = tid + kk * 256;
                float v = h[(size_t)(b0 + r) * NR + k];
                ((float*)&sm.l.hsp[r >> 1][k])[r & 1] = v;
            }
        }
        __syncthreads();

        ull acc[4] = {0ull, 0ull, 0ull, 0ull};
        const int kbase = kq << 8;
#pragma unroll 8
        for (int kk = 0; kk < 256; kk++) {
            int k = kbase + kk;
            float w = sw[(size_t)k * NC + j];
            ull wd = pack2(w, w);
#pragma unroll
            for (int p = 0; p < 4; p++)
                ffma2(acc[p], wd, *(const ull*)&sm.l.hsp[p][k]);
        }
        if (kq) {
#pragma unroll
            for (int p = 0; p < 4; p++) {
                float x, y; unpack2(acc[p], x, y);
                sm.l.part[p][j] = make_float2(x, y);
            }
        }
        __syncthreads();
        if (!kq) {
#pragma unroll
            for (int p = 0; p < 4; p++) {
                float x, y; unpack2(acc[p], x, y);
                float2 p1 = sm.l.part[p][j];
                sm.l.lgs[2 * p + 0][j] = x + p1.x + bj;
                sm.l.lgs[2 * p + 1][j] = y + p1.y + bj;
            }
        }
        __syncthreads();

        {   // argmax: 8 warps -> 8 rows, first-max tie rule
            const int wid = tid >> 5, lane = tid & 31;
            float best = -INFINITY; int bi = 0;
            const int cbase = lane * 4;
#pragma unroll
            for (int cc = 0; cc < 4; cc++) {
                float v = sm.l.lgs[wid][cbase + cc];
                if (v > best) { best = v; bi = cbase + cc; }
            }
#pragma unroll
            for (int off = 16; off; off >>= 1) {
                float ov = __shfl_down_sync(0xffffffffu, best, off);
                int   oi = __shfl_down_sync(0xffffffffu, bi,   off);
                if (ov > best || (ov == best && oi < bi)) { best = ov; bi = oi; }
            }
            if (lane == 0) sm.l.amax[wid] = bi;
        }
        __syncthreads();

#pragma unroll
        for (int rr = 0; rr < 4; rr++) {
            int r = kq * 4 + rr;
            out[((size_t)(b0 + r) * NT + lt) * NC + j] = (j == sm.l.amax[r]) ? 1.f : 0.f;
        }
        __syncthreads();   // protect smem before next group
    }
}

// ---------------------------------------------------------------------------
// k_gemm: 272 blocks x 256 thr (2 blocks/SM co-resident, single wave).
// bid<256 -> partial GEMM chunk; bid>=256 -> logits(t-1).
// ---------------------------------------------------------------------------
__global__ void __launch_bounds__(256, 2) k_gemm(
    const float* __restrict__ rec,
    const float* __restrict__ sw,
    const float* __restrict__ sb,
    float* __restrict__ out, int t)
{
    __shared__ GemmSM sm;
    const int bid = blockIdx.x;
    if (bid < 256) {
        do_gemm(sm, rec, t, bid);
    } else if (t > 0) {
        do_logits256(sm, sw, sb, out, t - 1, bid - 256);
    }
}

// ---------------------------------------------------------------------------
// k_gates: z = Z[t] + ((P0+P1)+(P2+P3)); LSTM nonlinearity; h_out, c update.
// 128 blocks x 512 thr; thread -> (b, j-quad) with float4 loads.
// ---------------------------------------------------------------------------
__global__ void __launch_bounds__(512) k_gates(int t)
{
    const int gid = blockIdx.x * 512 + threadIdx.x;   // 0..65535
    const int b = gid >> 7;                           // 0..511
    const int j = (gid & 127) * 4;                    // 0..508
    float* __restrict__ h_out = g_h[(t & 1) ^ 1];
    const size_t zb = ((size_t)t * NB + b) * NG + j;
    const size_t pb = (size_t)b * NG + j;

    float4 z[4];
#pragma unroll
    for (int g = 0; g < 4; g++) {
        float4 zz = *(const float4*)&g_Z[zb + g * NR];
        float4 p0 = *(const float4*)&g_P[0][pb + g * NR];
        float4 p1 = *(const float4*)&g_P[1][pb + g * NR];
        float4 p2 = *(const float4*)&g_P[2][pb + g * NR];
        float4 p3 = *(const float4*)&g_P[3][pb + g * NR];
        z[g].x = zz.x + ((p0.x + p1.x) + (p2.x + p3.x));
        z[g].y = zz.y + ((p0.y + p1.y) + (p2.y + p3.y));
        z[g].z = zz.z + ((p0.z + p1.z) + (p2.z + p3.z));
        z[g].w = zz.w + ((p0.w + p1.w) + (p2.w + p3.w));
    }
    const int ci = b * NR + j;
    float4 cold = *(const float4*)&g_c[ci];
    float4 cn, hn;
    {
        float si = 1.f / (1.f + expf(-z[0].x));
        float sf = 1.f / (1.f + expf(-z[1].x));
        float so = 1.f / (1.f + expf(-z[3].x));
        float tg = tanhf(z[2].x);
        cn.x = sf * cold.x + si * tg;
        hn.x = so * tanhf(cn.x);
    }
    {
        float si = 1.f / (1.f + expf(-z[0].y));
        float sf = 1.f / (1.f + expf(-z[1].y));
        float so = 1.f / (1.f + expf(-z[3].y));
        float tg = tanhf(z[2].y);
        cn.y = sf * cold.y + si * tg;
        hn.y = so * tanhf(cn.y);
    }
    {
        float si = 1.f / (1.f + expf(-z[0].z));
        float sf = 1.f / (1.f + expf(-z[1].z));
        float so = 1.f / (1.f + expf(-z[3].z));
        float tg = tanhf(z[2].z);
        cn.z = sf * cold.z + si * tg;
        hn.z = so * tanhf(cn.z);
    }
    {
        float si = 1.f / (1.f + expf(-z[0].w));
        float sf = 1.f / (1.f + expf(-z[1].w));
        float so = 1.f / (1.f + expf(-z[3].w));
        float tg = tanhf(z[2].w);
        cn.w = sf * cold.w + si * tg;
        hn.w = so * tanhf(cn.w);
    }
    *(float4*)&g_c[ci] = cn;
    *(float4*)&h_out[ci] = hn;
}

// ---------------------------------------------------------------------------
// Tail: blocks 0..15 logits(NT-1); blocks 16..31 finalize h/c copy (float4).
// ---------------------------------------------------------------------------
__global__ void __launch_bounds__(256) k_tail(
    const float* __restrict__ sw,
    const float* __restrict__ sb,
    float* __restrict__ out)
{
    __shared__ GemmSM sm;
    const int bid = blockIdx.x;
    if (bid < 16) {
        do_logits256(sm, sw, sb, out, NT - 1, bid);
    } else {
        float* oh = out + (size_t)NB * NT * NC;
        float* oc = oh + (size_t)NB * NR;
        const int n4 = NB * NR / 4;                 // 65536 float4s
        for (int i = (bid - 16) * 256 + threadIdx.x; i < n4; i += 16 * 256) {
            ((float4*)oh)[i] = ((const float4*)g_h[0])[i];   // NT & 1 == 0
            ((float4*)oc)[i] = ((const float4*)g_c)[i];
        }
    }
}

// ---------------------------------------------------------------------------
extern "C" void kernel_launch(void* const* d_in, const int* in_sizes, int n_in,
                              void* d_out, int out_size)
{
    const float* f_pool = (const float*)d_in[0];
    const float* gt     = (const float*)d_in[1];
    const float* W      = (const float*)d_in[2];
    const float* rec    = (const float*)d_in[3];
    const float* bias   = (const float*)d_in[4];
    const float* sw     = (const float*)d_in[5];
    const float* sb     = (const float*)d_in[6];
    float* out = (float*)d_out;

    k_init<<<(NB * NR + 255) / 256, 256>>>();
    k_precompute<<<dim3(16, 128), 256>>>(f_pool, gt, W, bias);
    for (int t = 0; t < NT; t++) {
        k_gemm<<<272, 256>>>(rec, sw, sb, out, t);
        k_gates<<<128, 512>>>(t);
    }
    k_tail<<<32, 256>>>(sw, sb, out);
}

// round 14
// speedup vs baseline: 1.1908x; 1.1908x over previous
#include <cuda_runtime.h>
#include <math.h>

#define NB 512      // batch
#define NT 32       // timesteps
#define ND 512      // depth
#define NC 128      // classes
#define NR 512      // rnn hidden
#define NG 2048     // 4*rnn
#define KX 640      // depth + ncc

typedef unsigned long long ull;

__device__ float g_Z[(size_t)NB * NT * NG];   // 128 MiB
__device__ float g_P[2][(size_t)NB * NG];     // 8 MiB partial gate sums
__device__ float g_h[2][NB * NR];
__device__ float g_c[NB * NR];

// ---------------------------------------------------------------------------
__device__ __forceinline__ ull pack2(float x, float y) {
    ull r; asm("mov.b64 %0, {%1, %2};" : "=l"(r) : "f"(x), "f"(y)); return r;
}
__device__ __forceinline__ void unpack2(ull v, float& x, float& y) {
    asm("mov.b64 {%0, %1}, %2;" : "=f"(x), "=f"(y) : "l"(v));
}
__device__ __forceinline__ void ffma2(ull& d, ull a, ull b) {
    asm("fma.rn.f32x2 %0, %1, %2, %0;" : "+l"(d) : "l"(a), "l"(b));
}
// fast activations (MUFU EX2/RCP, ~2 ulp)
__device__ __forceinline__ float fsig(float x) {
    return __fdividef(1.f, 1.f + __expf(-x));
}
__device__ __forceinline__ float ftanh(float x) {
    return __fdividef(2.f, 1.f + __expf(-2.f * x)) - 1.f;
}

// ---------------------------------------------------------------------------
// Precompute Z = X @ kernel + bias    (M=16384, K=640, N=2048)  [proven]
// ---------------------------------------------------------------------------
__global__ void __launch_bounds__(256, 2) k_precompute(
    const float* __restrict__ f_pool,
    const float* __restrict__ gt,
    const float* __restrict__ W,
    const float* __restrict__ bias)
{
    __shared__ float As[16][128];
    __shared__ float Bs[16][128];
    const int tid = threadIdx.x;
    const int tx = tid & 15, ty = tid >> 4;
    const int m0 = blockIdx.y * 128;
    const int n0 = blockIdx.x * 128;
    const int t  = m0 >> 9;
    const int b0 = m0 & 511;

    ull acc[8][4];
#pragma unroll
    for (int i = 0; i < 8; i++)
#pragma unroll
        for (int p = 0; p < 4; p++) acc[i][p] = 0ull;

    const int aIdx = tid * 2;

    for (int k0 = 0; k0 < KX; k0 += 16) {
#pragma unroll
        for (int l = 0; l < 2; l++) {
            int q   = aIdx + l;
            int row = q >> 2;
            int kq  = (q & 3) << 2;
            int k   = k0 + kq;
            float4 v;
            if (k < ND) {
                v = *(const float4*)(f_pool + ((size_t)(b0 + row) * NT + t) * ND + k);
            } else if (t == 0) {
                v = make_float4(0.f, 0.f, 0.f, 0.f);
            } else {
                v = *(const float4*)(gt + ((size_t)(b0 + row) * NT + (t - 1)) * NC + (k - ND));
            }
            As[kq + 0][row] = v.x; As[kq + 1][row] = v.y;
            As[kq + 2][row] = v.z; As[kq + 3][row] = v.w;
        }
#pragma unroll
        for (int l = 0; l < 2; l++) {
            int q   = aIdx + l;
            int row = q >> 5;
            int cq  = (q & 31) << 2;
            *(float4*)&Bs[row][cq] =
                *(const float4*)(W + (size_t)(k0 + row) * NG + n0 + cq);
        }
        __syncthreads();

#pragma unroll
        for (int k = 0; k < 16; k++) {
            float a[8];
            *(float4*)&a[0] = *(float4*)&As[k][ty * 4];
            *(float4*)&a[4] = *(float4*)&As[k][64 + ty * 4];
            ull bp[4];
            bp[0] = *(const ull*)&Bs[k][tx * 4];
            bp[1] = *(const ull*)&Bs[k][tx * 4 + 2];
            bp[2] = *(const ull*)&Bs[k][64 + tx * 4];
            bp[3] = *(const ull*)&Bs[k][64 + tx * 4 + 2];
            ull ad[8];
#pragma unroll
            for (int i = 0; i < 8; i++) ad[i] = pack2(a[i], a[i]);
#pragma unroll
            for (int i = 0; i < 8; i++)
#pragma unroll
                for (int p = 0; p < 4; p++)
                    ffma2(acc[i][p], ad[i], bp[p]);
        }
        __syncthreads();
    }

#pragma unroll
    for (int ih = 0; ih < 2; ih++)
#pragma unroll
    for (int ii = 0; ii < 4; ii++) {
        int m = m0 + ih * 64 + ty * 4 + ii;
        int i = ih * 4 + ii;
#pragma unroll
        for (int jh = 0; jh < 2; jh++) {
            int n = n0 + jh * 64 + tx * 4;
            float4 v;
            unpack2(acc[i][jh * 2 + 0], v.x, v.y);
            unpack2(acc[i][jh * 2 + 1], v.z, v.w);
            v.x += bias[n + 0]; v.y += bias[n + 1];
            v.z += bias[n + 2]; v.w += bias[n + 3];
            *(float4*)&g_Z[(size_t)m * NG + n] = v;
        }
    }
}

// ---------------------------------------------------------------------------
// Shared overlay for k_gemm (GEMM role 32 KB double-buffered; logits ~24.6 KB)
// ---------------------------------------------------------------------------
union GemmSM {
    struct { float As[2][16][128]; float Bs[2][16][128]; } g;
    struct { float2 hsp[4][NR]; float2 part[4][NC];
             float lgs[8][NC]; int amax[8]; } l;
};

// ---------------------------------------------------------------------------
// GEMM role: partial h @ rec over one K-chunk of 256.
// 128x128 tile, 8x8/thread, BK=16, DOUBLE-BUFFERED smem (1 sync/tile),
// register prefetch. bid: chunk = bid>>6, tile = bid&63.
// ---------------------------------------------------------------------------
__device__ void do_gemm(GemmSM& sm, const float* __restrict__ rec,
                        int t, int bid)
{
    const int tid = threadIdx.x;          // 256
    const int tx = tid & 15, ty = tid >> 4;
    const int chunk = bid >> 6;
    const int tile  = bid & 63;
    const int m0 = (tile >> 4) * 128;
    const int n0 = (tile & 15) * 128;
    const int kb = chunk * 256;
    const float* __restrict__ h_in = g_h[t & 1];
    float* __restrict__ P = g_P[chunk];

    ull acc[8][4];
#pragma unroll
    for (int i = 0; i < 8; i++)
#pragma unroll
        for (int p = 0; p < 4; p++) acc[i][p] = 0ull;

    const int q0 = tid * 2, q1 = q0 + 1;
    const int ar0 = q0 >> 2, ak0 = (q0 & 3) << 2;
    const int ar1 = q1 >> 2, ak1 = (q1 & 3) << 2;
    const int br0 = q0 >> 5, bc0 = (q0 & 31) << 2;
    const int br1 = q1 >> 5, bc1 = (q1 & 31) << 2;
    const float* ap0 = h_in + (size_t)(m0 + ar0) * NR + kb + ak0;
    const float* ap1 = h_in + (size_t)(m0 + ar1) * NR + kb + ak1;
    const float* bq0 = rec + (size_t)(kb + br0) * NG + n0 + bc0;
    const float* bq1 = rec + (size_t)(kb + br1) * NG + n0 + bc1;

    // tile 0 -> buffer 0
    {
        float4 ra0 = *(const float4*)ap0;
        float4 ra1 = *(const float4*)ap1;
        float4 rb0 = *(const float4*)bq0;
        float4 rb1 = *(const float4*)bq1;
        sm.g.As[0][ak0 + 0][ar0] = ra0.x; sm.g.As[0][ak0 + 1][ar0] = ra0.y;
        sm.g.As[0][ak0 + 2][ar0] = ra0.z; sm.g.As[0][ak0 + 3][ar0] = ra0.w;
        sm.g.As[0][ak1 + 0][ar1] = ra1.x; sm.g.As[0][ak1 + 1][ar1] = ra1.y;
        sm.g.As[0][ak1 + 2][ar1] = ra1.z; sm.g.As[0][ak1 + 3][ar1] = ra1.w;
        *(float4*)&sm.g.Bs[0][br0][bc0] = rb0;
        *(float4*)&sm.g.Bs[0][br1][bc1] = rb1;
    }
    __syncthreads();

    for (int tl = 0; tl < 16; tl++) {
        const int cur = tl & 1;
        float4 ra0, ra1, rb0, rb1;
        if (tl < 15) {                       // prefetch next tile (overlaps FMA)
            const int ko = (tl + 1) * 16;
            ra0 = *(const float4*)(ap0 + ko);
            ra1 = *(const float4*)(ap1 + ko);
            rb0 = *(const float4*)(bq0 + (size_t)ko * NG);
            rb1 = *(const float4*)(bq1 + (size_t)ko * NG);
        }

#pragma unroll
        for (int k = 0; k < 16; k++) {
            float a[8];
            *(float4*)&a[0] = *(float4*)&sm.g.As[cur][k][ty * 4];
            *(float4*)&a[4] = *(float4*)&sm.g.As[cur][k][64 + ty * 4];
            ull bp[4];
            bp[0] = *(const ull*)&sm.g.Bs[cur][k][tx * 4];
            bp[1] = *(const ull*)&sm.g.Bs[cur][k][tx * 4 + 2];
            bp[2] = *(const ull*)&sm.g.Bs[cur][k][64 + tx * 4];
            bp[3] = *(const ull*)&sm.g.Bs[cur][k][64 + tx * 4 + 2];
            ull ad[8];
#pragma unroll
            for (int i = 0; i < 8; i++) ad[i] = pack2(a[i], a[i]);
#pragma unroll
            for (int i = 0; i < 8; i++)
#pragma unroll
                for (int p = 0; p < 4; p++)
                    ffma2(acc[i][p], ad[i], bp[p]);
        }

        if (tl < 15) {                       // store into idle buffer
            const int nxt = cur ^ 1;
            sm.g.As[nxt][ak0 + 0][ar0] = ra0.x; sm.g.As[nxt][ak0 + 1][ar0] = ra0.y;
            sm.g.As[nxt][ak0 + 2][ar0] = ra0.z; sm.g.As[nxt][ak0 + 3][ar0] = ra0.w;
            sm.g.As[nxt][ak1 + 0][ar1] = ra1.x; sm.g.As[nxt][ak1 + 1][ar1] = ra1.y;
            sm.g.As[nxt][ak1 + 2][ar1] = ra1.z; sm.g.As[nxt][ak1 + 3][ar1] = ra1.w;
            *(float4*)&sm.g.Bs[nxt][br0][bc0] = rb0;
            *(float4*)&sm.g.Bs[nxt][br1][bc1] = rb1;
        }
        __syncthreads();
    }

#pragma unroll
    for (int ih = 0; ih < 2; ih++)
#pragma unroll
    for (int ii = 0; ii < 4; ii++) {
        int m = m0 + ih * 64 + ty * 4 + ii;
        int i = ih * 4 + ii;
#pragma unroll
        for (int jh = 0; jh < 2; jh++) {
            int n = n0 + jh * 64 + tx * 4;
            float4 v;
            unpack2(acc[i][jh * 2 + 0], v.x, v.y);
            unpack2(acc[i][jh * 2 + 1], v.z, v.w);
            *(float4*)&P[(size_t)m * NG + n] = v;
        }
    }
}

// ---------------------------------------------------------------------------
// Logits role (256 thr): 32 rows/block in 4 groups of 8; 2-way k-split.
// 16 blocks. lt = emitted timestep; reads g_h[(lt+1)&1].
// ---------------------------------------------------------------------------
__device__ void do_logits256(GemmSM& sm,
                             const float* __restrict__ sw,
                             const float* __restrict__ sb,
                             float* __restrict__ out, int lt, int lbid)
{
    const int tid = threadIdx.x;          // 256
    const int j   = tid & 127;
    const int kq  = tid >> 7;             // 0/1
    const float* __restrict__ h = g_h[(lt + 1) & 1];
    const float bj = sb[j];

    for (int grp = 0; grp < 4; grp++) {
        const int b0 = lbid * 32 + grp * 8;

#pragma unroll
        for (int r = 0; r < 8; r++) {
#pragma unroll
            for (int kk = 0; kk < 2; kk++) {
                int k = tid + kk * 256;
                float v = h[(size_t)(b0 + r) * NR + k];
                ((float*)&sm.l.hsp[r >> 1][k])[r & 1] = v;
            }
        }
        __syncthreads();

        ull acc[4] = {0ull, 0ull, 0ull, 0ull};
        const int kbase = kq << 8;
#pragma unroll 8
        for (int kk = 0; kk < 256; kk++) {
            int k = kbase + kk;
            float w = sw[(size_t)k * NC + j];
            ull wd = pack2(w, w);
#pragma unroll
            for (int p = 0; p < 4; p++)
                ffma2(acc[p], wd, *(const ull*)&sm.l.hsp[p][k]);
        }
        if (kq) {
#pragma unroll
            for (int p = 0; p < 4; p++) {
                float x, y; unpack2(acc[p], x, y);
                sm.l.part[p][j] = make_float2(x, y);
            }
        }
        __syncthreads();
        if (!kq) {
#pragma unroll
            for (int p = 0; p < 4; p++) {
                float x, y; unpack2(acc[p], x, y);
                float2 p1 = sm.l.part[p][j];
                sm.l.lgs[2 * p + 0][j] = x + p1.x + bj;
                sm.l.lgs[2 * p + 1][j] = y + p1.y + bj;
            }
        }
        __syncthreads();

        {   // argmax: 8 warps -> 8 rows, first-max tie rule
            const int wid = tid >> 5, lane = tid & 31;
            float best = -INFINITY; int bi = 0;
            const int cbase = lane * 4;
#pragma unroll
            for (int cc = 0; cc < 4; cc++) {
                float v = sm.l.lgs[wid][cbase + cc];
                if (v > best) { best = v; bi = cbase + cc; }
            }
#pragma unroll
            for (int off = 16; off; off >>= 1) {
                float ov = __shfl_down_sync(0xffffffffu, best, off);
                int   oi = __shfl_down_sync(0xffffffffu, bi,   off);
                if (ov > best || (ov == best && oi < bi)) { best = ov; bi = oi; }
            }
            if (lane == 0) sm.l.amax[wid] = bi;
        }
        __syncthreads();

#pragma unroll
        for (int rr = 0; rr < 4; rr++) {
            int r = kq * 4 + rr;
            out[((size_t)(b0 + r) * NT + lt) * NC + j] = (j == sm.l.amax[r]) ? 1.f : 0.f;
        }
        __syncthreads();   // protect smem before next group
    }
}

// ---------------------------------------------------------------------------
// k_gemm: 144 blocks x 256 thr. bid<128 -> partial GEMM; bid>=128 -> logits(t-1)
// ---------------------------------------------------------------------------
__global__ void __launch_bounds__(256) k_gemm(
    const float* __restrict__ rec,
    const float* __restrict__ sw,
    const float* __restrict__ sb,
    float* __restrict__ out, int t)
{
    __shared__ GemmSM sm;
    const int bid = blockIdx.x;
    if (bid < 128) {
        do_gemm(sm, rec, t, bid);
    } else {
        do_logits256(sm, sw, sb, out, t - 1, bid - 128);   // t >= 1 always
    }
}

// ---------------------------------------------------------------------------
// k_gates: z = Z[t] + (P0+P1) [or Z only at t=0]; LSTM nonlinearity.
// 128 blocks x 512 thr; thread -> (b, j-quad) with float4 loads.
// ---------------------------------------------------------------------------
__global__ void __launch_bounds__(512) k_gates(int t, int first)
{
    const int gid = blockIdx.x * 512 + threadIdx.x;   // 0..65535
    const int b = gid >> 7;                           // 0..511
    const int j = (gid & 127) * 4;                    // 0..508
    float* __restrict__ h_out = g_h[(t & 1) ^ 1];
    const size_t zb = ((size_t)t * NB + b) * NG + j;
    const size_t pb = (size_t)b * NG + j;

    float4 z[4];
#pragma unroll
    for (int g = 0; g < 4; g++) {
        float4 zz = *(const float4*)&g_Z[zb + g * NR];
        if (first) {
            z[g] = zz;
        } else {
            float4 p0 = *(const float4*)&g_P[0][pb + g * NR];
            float4 p1 = *(const float4*)&g_P[1][pb + g * NR];
            z[g].x = zz.x + (p0.x + p1.x);
            z[g].y = zz.y + (p0.y + p1.y);
            z[g].z = zz.z + (p0.z + p1.z);
            z[g].w = zz.w + (p0.w + p1.w);
        }
    }
    const int ci = b * NR + j;
    float4 cold = first ? make_float4(0.f, 0.f, 0.f, 0.f)
                        : *(const float4*)&g_c[ci];
    float4 cn, hn;
    {
        float si = fsig(z[0].x), sf = fsig(z[1].x), so = fsig(z[3].x);
        float tg = ftanh(z[2].x);
        cn.x = sf * cold.x + si * tg;
        hn.x = so * ftanh(cn.x);
    }
    {
        float si = fsig(z[0].y), sf = fsig(z[1].y), so = fsig(z[3].y);
        float tg = ftanh(z[2].y);
        cn.y = sf * cold.y + si * tg;
        hn.y = so * ftanh(cn.y);
    }
    {
        float si = fsig(z[0].z), sf = fsig(z[1].z), so = fsig(z[3].z);
        float tg = ftanh(z[2].z);
        cn.z = sf * cold.z + si * tg;
        hn.z = so * ftanh(cn.z);
    }
    {
        float si = fsig(z[0].w), sf = fsig(z[1].w), so = fsig(z[3].w);
        float tg = ftanh(z[2].w);
        cn.w = sf * cold.w + si * tg;
        hn.w = so * ftanh(cn.w);
    }
    *(float4*)&g_c[ci] = cn;
    *(float4*)&h_out[ci] = hn;
}

// ---------------------------------------------------------------------------
// Tail: blocks 0..15 logits(NT-1); blocks 16..31 finalize h/c copy (float4).
// ---------------------------------------------------------------------------
__global__ void __launch_bounds__(256) k_tail(
    const float* __restrict__ sw,
    const float* __restrict__ sb,
    float* __restrict__ out)
{
    __shared__ GemmSM sm;
    const int bid = blockIdx.x;
    if (bid < 16) {
        do_logits256(sm, sw, sb, out, NT - 1, bid);
    } else {
        float* oh = out + (size_t)NB * NT * NC;
        float* oc = oh + (size_t)NB * NR;
        const int n4 = NB * NR / 4;                 // 65536 float4s
        for (int i = (bid - 16) * 256 + threadIdx.x; i < n4; i += 16 * 256) {
            ((float4*)oh)[i] = ((const float4*)g_h[0])[i];   // NT & 1 == 0
            ((float4*)oc)[i] = ((const float4*)g_c)[i];
        }
    }
}

// ---------------------------------------------------------------------------
extern "C" void kernel_launch(void* const* d_in, const int* in_sizes, int n_in,
                              void* d_out, int out_size)
{
    const float* f_pool = (const float*)d_in[0];
    const float* gt     = (const float*)d_in[1];
    const float* W      = (const float*)d_in[2];
    const float* rec    = (const float*)d_in[3];
    const float* bias   = (const float*)d_in[4];
    const float* sw     = (const float*)d_in[5];
    const float* sb     = (const float*)d_in[6];
    float* out = (float*)d_out;

    k_precompute<<<dim3(16, 128), 256>>>(f_pool, gt, W, bias);
    // t = 0: h0 = 0 -> recurrent GEMM is exactly zero; gates use Z only.
    k_gates<<<128, 512>>>(0, 1);
    for (int t = 1; t < NT; t++) {
        k_gemm<<<144, 256>>>(rec, sw, sb, out, t);   // + logits(t-1) hidden
        k_gates<<<128, 512>>>(t, 0);
    }
    k_tail<<<32, 256>>>(sw, sb, out);
}

// round 17
// speedup vs baseline: 1.2051x; 1.0121x over previous
#include <cuda_runtime.h>
#include <cuda_bf16.h>
#include <stdint.h>
#include <math.h>

#define NB 512      // batch
#define NT 32       // timesteps
#define ND 512      // depth
#define NC 128      // classes
#define NR 512      // rnn hidden
#define NG 2048     // 4*rnn
#define KX 640      // depth + ncc
#define MTOT 16384  // NB*NT

typedef unsigned long long ull;

__device__ float g_Z[(size_t)MTOT * NG];      // 128 MiB
__device__ float g_P[2][(size_t)NB * NG];     // 8 MiB partial gate sums
__device__ float g_h[2][NB * NR];
__device__ float g_c[NB * NR];
// bf16 3-way splits of X (gathered input, [m][k]) and W^T ([n][k])
__device__ __nv_bfloat16 g_Xs[3][(size_t)MTOT * KX];
__device__ __nv_bfloat16 g_Ws[3][(size_t)NG * KX];

// ---------------------------------------------------------------------------
__device__ __forceinline__ ull pack2(float x, float y) {
    ull r; asm("mov.b64 %0, {%1, %2};" : "=l"(r) : "f"(x), "f"(y)); return r;
}
__device__ __forceinline__ void unpack2(ull v, float& x, float& y) {
    asm("mov.b64 {%0, %1}, %2;" : "=f"(x), "=f"(y) : "l"(v));
}
__device__ __forceinline__ void ffma2(ull& d, ull a, ull b) {
    asm("fma.rn.f32x2 %0, %1, %2, %0;" : "+l"(d) : "l"(a), "l"(b));
}
__device__ __forceinline__ float fsig(float x) {
    return __fdividef(1.f, 1.f + __expf(-x));
}
__device__ __forceinline__ float ftanh(float x) {
    return __fdividef(2.f, 1.f + __expf(-2.f * x)) - 1.f;
}
__device__ __forceinline__ uint32_t smem_u32(const void* p) {
    uint32_t a;
    asm("{ .reg .u64 t; cvta.to.shared.u64 t, %1; cvt.u32.u64 %0, t; }"
        : "=r"(a) : "l"(p));
    return a;
}
__device__ __forceinline__ void ldsm_x4(uint32_t* r, uint32_t addr) {
    asm volatile("ldmatrix.sync.aligned.m8n8.x4.shared.b16 {%0,%1,%2,%3}, [%4];"
                 : "=r"(r[0]), "=r"(r[1]), "=r"(r[2]), "=r"(r[3]) : "r"(addr));
}
__device__ __forceinline__ void mma_bf16(float* d, const uint32_t* a,
                                         const uint32_t* b) {
    asm volatile(
        "mma.sync.aligned.m16n8k16.row.col.f32.bf16.bf16.f32 "
        "{%0,%1,%2,%3}, {%4,%5,%6,%7}, {%8,%9}, {%0,%1,%2,%3};"
        : "+f"(d[0]), "+f"(d[1]), "+f"(d[2]), "+f"(d[3])
        : "r"(a[0]), "r"(a[1]), "r"(a[2]), "r"(a[3]), "r"(b[0]), "r"(b[1]));
}

// ---------------------------------------------------------------------------
// bf16 3-way split
// ---------------------------------------------------------------------------
__device__ __forceinline__ void split3(float v, __nv_bfloat16& h,
                                       __nv_bfloat16& m, __nv_bfloat16& l) {
    h = __float2bfloat16(v);
    float r = v - __bfloat162float(h);
    m = __float2bfloat16(r);
    l = __float2bfloat16(r - __bfloat162float(m));
}

// X (gathered [f_pool | prev gt]) -> g_Xs[3], layout [m][k], m = t*512 + b
__global__ void __launch_bounds__(256) k_convert_x(
    const float* __restrict__ f_pool, const float* __restrict__ gt)
{
    int gid = blockIdx.x * 256 + threadIdx.x;     // 16384*160
    int m = gid / 160;
    int k = (gid - m * 160) * 4;
    int t = m >> 9, b = m & 511;
    float4 v;
    if (k < ND) {
        v = *(const float4*)(f_pool + ((size_t)b * NT + t) * ND + k);
    } else if (t == 0) {
        v = make_float4(0.f, 0.f, 0.f, 0.f);
    } else {
        v = *(const float4*)(gt + ((size_t)b * NT + (t - 1)) * NC + (k - ND));
    }
    size_t o = (size_t)m * KX + k;
    float vv[4] = {v.x, v.y, v.z, v.w};
    __nv_bfloat16 h[4], md[4], lo[4];
#pragma unroll
    for (int i = 0; i < 4; i++) split3(vv[i], h[i], md[i], lo[i]);
    *(uint2*)&g_Xs[0][o] = *(uint2*)h;
    *(uint2*)&g_Xs[1][o] = *(uint2*)md;
    *(uint2*)&g_Xs[2][o] = *(uint2*)lo;
}

// W [k][n] -> W^T splits [n][k]
__global__ void __launch_bounds__(256) k_convert_w(const float* __restrict__ W)
{
    int gid = blockIdx.x * 256 + threadIdx.x;     // 640*512
    int k = gid / 512;
    int n = (gid - k * 512) * 4;
    float4 v = *(const float4*)(W + (size_t)k * NG + n);
    float vv[4] = {v.x, v.y, v.z, v.w};
#pragma unroll
    for (int i = 0; i < 4; i++) {
        __nv_bfloat16 h, m, l;
        split3(vv[i], h, m, l);
        size_t o = (size_t)(n + i) * KX + k;
        g_Ws[0][o] = h; g_Ws[1][o] = m; g_Ws[2][o] = l;
    }
}

// ---------------------------------------------------------------------------
// Precompute Z = X @ W + bias via mma.sync bf16 6-term split.
// Block 128m x 256n, 512 thr (16 warps, warp tile 64x32). K tiles of 32.
// smem rows padded to 80 B (40 bf16): conflict-free ldmatrix.
//   A split s: offset s*10240, row r at r*80          (128 rows)
//   B split s: offset 30720 + s*20480, row n at n*80  (256 rows)
// ---------------------------------------------------------------------------
#define PRE_SMEM_TOTAL 92160

__global__ void __launch_bounds__(512) k_pre_mma(const float* __restrict__ bias)
{
    extern __shared__ char smem[];
    const int tid = threadIdx.x;
    const int wid = tid >> 5, lane = tid & 31;
    const int n0 = blockIdx.x * 256;
    const int m0 = blockIdx.y * 128;
    const int warp_m = wid >> 3;          // 0-1
    const int warp_n = wid & 7;           // 0-7
    const uint32_t sbase = smem_u32(smem);

    float acc[4][4][4];                   // [mi][nj][frag]
#pragma unroll
    for (int i = 0; i < 4; i++)
#pragma unroll
        for (int j = 0; j < 4; j++)
#pragma unroll
            for (int q = 0; q < 4; q++) acc[i][j][q] = 0.f;

    // ldmatrix lane-address components (constant across k-iters)
    const int a_row = warp_m * 64 + (lane & 15);         // + mi*16
    const int a_kh  = (lane >> 4) * 16;                  // byte offset of k-half
    const int b_n   = warp_n * 32 + ((lane >> 4) << 3) + (lane & 7);  // + pair*16
    const int b_kh  = ((lane >> 3) & 1) * 16;

    for (int ki = 0; ki < 20; ki++) {
        const int kb = ki * 32;
        // ---- stage: 4608 16B chunks (A 1536, B 3072)
#pragma unroll
        for (int it = 0; it < 9; it++) {
            int u = tid + it * 512;
            if (u < 4608) {
                if (u < 1536) {
                    int s = u / 512, w = u - s * 512;
                    int r = w >> 2, hf = w & 3;
                    *(uint4*)(smem + s * 10240 + r * 80 + hf * 16) =
                        *(const uint4*)(g_Xs[s] + (size_t)(m0 + r) * KX + kb + hf * 8);
                } else {
                    int v = u - 1536;
                    int s = v / 1024, w = v - s * 1024;
                    int r = w >> 2, hf = w & 3;
                    *(uint4*)(smem + 30720 + s * 20480 + r * 80 + hf * 16) =
                        *(const uint4*)(g_Ws[s] + (size_t)(n0 + r) * KX + kb + hf * 8);
                }
            }
        }
        __syncthreads();

        // ---- compute: 6 split-pairs, 2 k16 sub-tiles each
#pragma unroll
        for (int sa = 0; sa < 3; sa++) {
#pragma unroll
            for (int kk = 0; kk < 2; kk++) {
                uint32_t af[4][4];
#pragma unroll
                for (int mi = 0; mi < 4; mi++) {
                    uint32_t addr = sbase + sa * 10240 +
                                    (a_row + mi * 16) * 80 + kk * 32 + a_kh;
                    ldsm_x4(af[mi], addr);
                }
                const int nsb = 3 - sa;   // sa=0:3, sa=1:2, sa=2:1
#pragma unroll
                for (int sb = 0; sb < 3; sb++) {
                    if (sb >= nsb) break;
                    uint32_t bf[4][2];
#pragma unroll
                    for (int pr = 0; pr < 2; pr++) {
                        uint32_t r4[4];
                        uint32_t addr = sbase + 30720 + sb * 20480 +
                                        (b_n + pr * 16) * 80 + kk * 32 + b_kh;
                        ldsm_x4(r4, addr);
                        bf[pr * 2 + 0][0] = r4[0]; bf[pr * 2 + 0][1] = r4[1];
                        bf[pr * 2 + 1][0] = r4[2]; bf[pr * 2 + 1][1] = r4[3];
                    }
#pragma unroll
                    for (int mi = 0; mi < 4; mi++)
#pragma unroll
                        for (int nj = 0; nj < 4; nj++)
                            mma_bf16(acc[mi][nj], af[mi], bf[nj]);
                }
            }
        }
        __syncthreads();
    }

    // ---- epilogue: + bias -> g_Z
    {
        const int qr = lane >> 2;
        const int qc = (lane & 3) * 2;
        const int nb = n0 + warp_n * 32;
#pragma unroll
        for (int mi = 0; mi < 4; mi++) {
            int m = m0 + warp_m * 64 + mi * 16 + qr;
            float* z0 = g_Z + (size_t)m * NG + nb;
            float* z1 = z0 + (size_t)8 * NG;
#pragma unroll
            for (int nj = 0; nj < 4; nj++) {
                int col = nj * 8 + qc;
                float b0 = bias[nb + col], b1 = bias[nb + col + 1];
                float2 v0 = make_float2(acc[mi][nj][0] + b0, acc[mi][nj][1] + b1);
                float2 v1 = make_float2(acc[mi][nj][2] + b0, acc[mi][nj][3] + b1);
                *(float2*)(z0 + col) = v0;
                *(float2*)(z1 + col) = v1;
            }
        }
    }
}

// ---------------------------------------------------------------------------
// Shared overlay for k_gemm (GEMM role 32 KB double-buffered; logits ~24.6 KB)
// ---------------------------------------------------------------------------
union GemmSM {
    struct { float As[2][16][128]; float Bs[2][16][128]; } g;
    struct { float2 hsp[4][NR]; float2 part[4][NC];
             float lgs[8][NC]; int amax[8]; } l;
};

// ---------------------------------------------------------------------------
// GEMM role: partial h @ rec over one K-chunk of 256.  [proven R14]
// ---------------------------------------------------------------------------
__device__ void do_gemm(GemmSM& sm, const float* __restrict__ rec,
                        int t, int bid)
{
    const int tid = threadIdx.x;
    const int tx = tid & 15, ty = tid >> 4;
    const int chunk = bid >> 6;
    const int tile  = bid & 63;
    const int m0 = (tile >> 4) * 128;
    const int n0 = (tile & 15) * 128;
    const int kb = chunk * 256;
    const float* __restrict__ h_in = g_h[t & 1];
    float* __restrict__ P = g_P[chunk];

    ull acc[8][4];
#pragma unroll
    for (int i = 0; i < 8; i++)
#pragma unroll
        for (int p = 0; p < 4; p++) acc[i][p] = 0ull;

    const int q0 = tid * 2, q1 = q0 + 1;
    const int ar0 = q0 >> 2, ak0 = (q0 & 3) << 2;
    const int ar1 = q1 >> 2, ak1 = (q1 & 3) << 2;
    const int br0 = q0 >> 5, bc0 = (q0 & 31) << 2;
    const int br1 = q1 >> 5, bc1 = (q1 & 31) << 2;
    const float* ap0 = h_in + (size_t)(m0 + ar0) * NR + kb + ak0;
    const float* ap1 = h_in + (size_t)(m0 + ar1) * NR + kb + ak1;
    const float* bq0 = rec + (size_t)(kb + br0) * NG + n0 + bc0;
    const float* bq1 = rec + (size_t)(kb + br1) * NG + n0 + bc1;

    {
        float4 ra0 = *(const float4*)ap0;
        float4 ra1 = *(const float4*)ap1;
        float4 rb0 = *(const float4*)bq0;
        float4 rb1 = *(const float4*)bq1;
        sm.g.As[0][ak0 + 0][ar0] = ra0.x; sm.g.As[0][ak0 + 1][ar0] = ra0.y;
        sm.g.As[0][ak0 + 2][ar0] = ra0.z; sm.g.As[0][ak0 + 3][ar0] = ra0.w;
        sm.g.As[0][ak1 + 0][ar1] = ra1.x; sm.g.As[0][ak1 + 1][ar1] = ra1.y;
        sm.g.As[0][ak1 + 2][ar1] = ra1.z; sm.g.As[0][ak1 + 3][ar1] = ra1.w;
        *(float4*)&sm.g.Bs[0][br0][bc0] = rb0;
        *(float4*)&sm.g.Bs[0][br1][bc1] = rb1;
    }
    __syncthreads();

    for (int tl = 0; tl < 16; tl++) {
        const int cur = tl & 1;
        float4 ra0, ra1, rb0, rb1;
        if (tl < 15) {
            const int ko = (tl + 1) * 16;
            ra0 = *(const float4*)(ap0 + ko);
            ra1 = *(const float4*)(ap1 + ko);
            rb0 = *(const float4*)(bq0 + (size_t)ko * NG);
            rb1 = *(const float4*)(bq1 + (size_t)ko * NG);
        }

#pragma unroll
        for (int k = 0; k < 16; k++) {
            float a[8];
            *(float4*)&a[0] = *(float4*)&sm.g.As[cur][k][ty * 4];
            *(float4*)&a[4] = *(float4*)&sm.g.As[cur][k][64 + ty * 4];
            ull bp[4];
            bp[0] = *(const ull*)&sm.g.Bs[cur][k][tx * 4];
            bp[1] = *(const ull*)&sm.g.Bs[cur][k][tx * 4 + 2];
            bp[2] = *(const ull*)&sm.g.Bs[cur][k][64 + tx * 4];
            bp[3] = *(const ull*)&sm.g.Bs[cur][k][64 + tx * 4 + 2];
            ull ad[8];
#pragma unroll
            for (int i = 0; i < 8; i++) ad[i] = pack2(a[i], a[i]);
#pragma unroll
            for (int i = 0; i < 8; i++)
#pragma unroll
                for (int p = 0; p < 4; p++)
                    ffma2(acc[i][p], ad[i], bp[p]);
        }

        if (tl < 15) {
            const int nxt = cur ^ 1;
            sm.g.As[nxt][ak0 + 0][ar0] = ra0.x; sm.g.As[nxt][ak0 + 1][ar0] = ra0.y;
            sm.g.As[nxt][ak0 + 2][ar0] = ra0.z; sm.g.As[nxt][ak0 + 3][ar0] = ra0.w;
            sm.g.As[nxt][ak1 + 0][ar1] = ra1.x; sm.g.As[nxt][ak1 + 1][ar1] = ra1.y;
            sm.g.As[nxt][ak1 + 2][ar1] = ra1.z; sm.g.As[nxt][ak1 + 3][ar1] = ra1.w;
            *(float4*)&sm.g.Bs[nxt][br0][bc0] = rb0;
            *(float4*)&sm.g.Bs[nxt][br1][bc1] = rb1;
        }
        __syncthreads();
    }

#pragma unroll
    for (int ih = 0; ih < 2; ih++)
#pragma unroll
    for (int ii = 0; ii < 4; ii++) {
        int m = m0 + ih * 64 + ty * 4 + ii;
        int i = ih * 4 + ii;
#pragma unroll
        for (int jh = 0; jh < 2; jh++) {
            int n = n0 + jh * 64 + tx * 4;
            float4 v;
            unpack2(acc[i][jh * 2 + 0], v.x, v.y);
            unpack2(acc[i][jh * 2 + 1], v.z, v.w);
            *(float4*)&P[(size_t)m * NG + n] = v;
        }
    }
}

// ---------------------------------------------------------------------------
// Logits role (256 thr): 32 rows/block in 4 groups of 8.  [proven R14]
// ---------------------------------------------------------------------------
__device__ void do_logits256(GemmSM& sm,
                             const float* __restrict__ sw,
                             const float* __restrict__ sb,
                             float* __restrict__ out, int lt, int lbid)
{
    const int tid = threadIdx.x;
    const int j   = tid & 127;
    const int kq  = tid >> 7;
    const float* __restrict__ h = g_h[(lt + 1) & 1];
    const float bj = sb[j];

    for (int grp = 0; grp < 4; grp++) {
        const int b0 = lbid * 32 + grp * 8;

#pragma unroll
        for (int r = 0; r < 8; r++) {
#pragma unroll
            for (int kk = 0; kk < 2; kk++) {
                int k = tid + kk * 256;
                float v = h[(size_t)(b0 + r) * NR + k];
                ((float*)&sm.l.hsp[r >> 1][k])[r & 1] = v;
            }
        }
        __syncthreads();

        ull acc[4] = {0ull, 0ull, 0ull, 0ull};
        const int kbase = kq << 8;
#pragma unroll 8
        for (int kk = 0; kk < 256; kk++) {
            int k = kbase + kk;
            float w = sw[(size_t)k * NC + j];
            ull wd = pack2(w, w);
#pragma unroll
            for (int p = 0; p < 4; p++)
                ffma2(acc[p], wd, *(const ull*)&sm.l.hsp[p][k]);
        }
        if (kq) {
#pragma unroll
            for (int p = 0; p < 4; p++) {
                float x, y; unpack2(acc[p], x, y);
                sm.l.part[p][j] = make_float2(x, y);
            }
        }
        __syncthreads();
        if (!kq) {
#pragma unroll
            for (int p = 0; p < 4; p++) {
                float x, y; unpack2(acc[p], x, y);
                float2 p1 = sm.l.part[p][j];
                sm.l.lgs[2 * p + 0][j] = x + p1.x + bj;
                sm.l.lgs[2 * p + 1][j] = y + p1.y + bj;
            }
        }
        __syncthreads();

        {
            const int wid = tid >> 5, lane = tid & 31;
            float best = -INFINITY; int bi = 0;
            const int cbase = lane * 4;
#pragma unroll
            for (int cc = 0; cc < 4; cc++) {
                float v = sm.l.lgs[wid][cbase + cc];
                if (v > best) { best = v; bi = cbase + cc; }
            }
#pragma unroll
            for (int off = 16; off; off >>= 1) {
                float ov = __shfl_down_sync(0xffffffffu, best, off);
                int   oi = __shfl_down_sync(0xffffffffu, bi,   off);
                if (ov > best || (ov == best && oi < bi)) { best = ov; bi = oi; }
            }
            if (lane == 0) sm.l.amax[wid] = bi;
        }
        __syncthreads();

#pragma unroll
        for (int rr = 0; rr < 4; rr++) {
            int r = kq * 4 + rr;
            out[((size_t)(b0 + r) * NT + lt) * NC + j] = (j == sm.l.amax[r]) ? 1.f : 0.f;
        }
        __syncthreads();
    }
}

// ---------------------------------------------------------------------------
__global__ void __launch_bounds__(256) k_gemm(
    const float* __restrict__ rec,
    const float* __restrict__ sw,
    const float* __restrict__ sb,
    float* __restrict__ out, int t)
{
    __shared__ GemmSM sm;
    const int bid = blockIdx.x;
    if (bid < 128) {
        do_gemm(sm, rec, t, bid);
    } else {
        do_logits256(sm, sw, sb, out, t - 1, bid - 128);
    }
}

// ---------------------------------------------------------------------------
__global__ void __launch_bounds__(512) k_gates(int t, int first)
{
    const int gid = blockIdx.x * 512 + threadIdx.x;
    const int b = gid >> 7;
    const int j = (gid & 127) * 4;
    float* __restrict__ h_out = g_h[(t & 1) ^ 1];
    const size_t zb = ((size_t)t * NB + b) * NG + j;
    const size_t pb = (size_t)b * NG + j;

    float4 z[4];
#pragma unroll
    for (int g = 0; g < 4; g++) {
        float4 zz = *(const float4*)&g_Z[zb + g * NR];
        if (first) {
            z[g] = zz;
        } else {
            float4 p0 = *(const float4*)&g_P[0][pb + g * NR];
            float4 p1 = *(const float4*)&g_P[1][pb + g * NR];
            z[g].x = zz.x + (p0.x + p1.x);
            z[g].y = zz.y + (p0.y + p1.y);
            z[g].z = zz.z + (p0.z + p1.z);
            z[g].w = zz.w + (p0.w + p1.w);
        }
    }
    const int ci = b * NR + j;
    float4 cold = first ? make_float4(0.f, 0.f, 0.f, 0.f)
                        : *(const float4*)&g_c[ci];
    float4 cn, hn;
    {
        float si = fsig(z[0].x), sf = fsig(z[1].x), so = fsig(z[3].x);
        float tg = ftanh(z[2].x);
        cn.x = sf * cold.x + si * tg;
        hn.x = so * ftanh(cn.x);
    }
    {
        float si = fsig(z[0].y), sf = fsig(z[1].y), so = fsig(z[3].y);
        float tg = ftanh(z[2].y);
        cn.y = sf * cold.y + si * tg;
        hn.y = so * ftanh(cn.y);
    }
    {
        float si = fsig(z[0].z), sf = fsig(z[1].z), so = fsig(z[3].z);
        float tg = ftanh(z[2].z);
        cn.z = sf * cold.z + si * tg;
        hn.z = so * ftanh(cn.z);
    }
    {
        float si = fsig(z[0].w), sf = fsig(z[1].w), so = fsig(z[3].w);
        float tg = ftanh(z[2].w);
        cn.w = sf * cold.w + si * tg;
        hn.w = so * ftanh(cn.w);
    }
    *(float4*)&g_c[ci] = cn;
    *(float4*)&h_out[ci] = hn;
}

// ---------------------------------------------------------------------------
__global__ void __launch_bounds__(256) k_tail(
    const float* __restrict__ sw,
    const float* __restrict__ sb,
    float* __restrict__ out)
{
    __shared__ GemmSM sm;
    const int bid = blockIdx.x;
    if (bid < 16) {
        do_logits256(sm, sw, sb, out, NT - 1, bid);
    } else {
        float* oh = out + (size_t)NB * NT * NC;
        float* oc = oh + (size_t)NB * NR;
        const int n4 = NB * NR / 4;
        for (int i = (bid - 16) * 256 + threadIdx.x; i < n4; i += 16 * 256) {
            ((float4*)oh)[i] = ((const float4*)g_h[0])[i];
            ((float4*)oc)[i] = ((const float4*)g_c)[i];
        }
    }
}

// ---------------------------------------------------------------------------
extern "C" void kernel_launch(void* const* d_in, const int* in_sizes, int n_in,
                              void* d_out, int out_size)
{
    const float* f_pool = (const float*)d_in[0];
    const float* gt     = (const float*)d_in[1];
    const float* W      = (const float*)d_in[2];
    const float* rec    = (const float*)d_in[3];
    const float* bias   = (const float*)d_in[4];
    const float* sw     = (const float*)d_in[5];
    const float* sb     = (const float*)d_in[6];
    float* out = (float*)d_out;

    cudaFuncSetAttribute(k_pre_mma, cudaFuncAttributeMaxDynamicSharedMemorySize,
                         PRE_SMEM_TOTAL);

    k_convert_w<<<(NG / 4) * KX / 256, 256>>>(W);
    k_convert_x<<<MTOT * (KX / 4) / 256, 256>>>(f_pool, gt);
    k_pre_mma<<<dim3(8, 128), 512, PRE_SMEM_TOTAL>>>(bias);
    k_gates<<<128, 512>>>(0, 1);
    for (int t = 1; t < NT; t++) {
        k_gemm<<<144, 256>>>(rec, sw, sb, out, t);
        k_gates<<<128, 512>>>(t, 0);
    }
    k_tail<<<32, 256>>>(sw, sb, out);
}